// round 15
// baseline (speedup 1.0000x reference)
#include <cuda_runtime.h>
#include <cuda_bf16.h>
#include <cuda_fp16.h>
#include <math.h>
#include <stdint.h>

// ---------------- problem dims (fixed) ----------------
#define Bb   4
#define Tt   1024
#define Dd   1024
#define Hh   16
#define HSs  64
#define DFF  4096
#define ROWS (Bb*Tt)      // 4096

// ---------------- scratch (device globals; no allocs allowed) ----------------
__device__ float g_hn [ROWS*Dd];
__device__ float g_qkv[ROWS*5120];     // q(2048) | k(2048) | v(1024), row stride 5120
__device__ float g_h2 [ROWS*Dd];
__device__ float g_m1 [ROWS*DFF];
__device__ float g_lam[32];

// fp16 activation split buffers (K-permuted layout)
#define NA_TOT (ROWS*DFF)
__device__ __half g_ahi[NA_TOT];
__device__ __half g_alo[NA_TOT];
__device__ __half g_bhi[NA_TOT];
__device__ __half g_blo[NA_TOT];

// fp16 weights (single term), transposed [N][K], K-permuted
#define NHW_TOT (24u*1024u*1024u)
__device__ __half g_wh[NHW_TOT];
#define OW_QS (0u)
#define OW_KS (2u*1024u*1024u)
#define OW_VS (4u*1024u*1024u)
#define OW_OS (5u*1024u*1024u)
#define OW_QC (6u*1024u*1024u)
#define OW_KC (8u*1024u*1024u)
#define OW_VC (10u*1024u*1024u)
#define OW_OC (11u*1024u*1024u)
#define OW_W1 (12u*1024u*1024u)
#define OW_W2 (16u*1024u*1024u)
#define OW_W3 (20u*1024u*1024u)

// K-permutation: within each 16-elem group, pair P (elems 2P,2P+1) -> pair np(P)
// np(P) = P<4 ? 2P : 2P-7
__device__ __host__ __forceinline__ int knp(int P) { return (P < 4) ? (2*P) : (2*P - 7); }

// ================= small helpers =================
__device__ __forceinline__ uint32_t smem_u32(const void* p) {
    uint32_t a;
    asm("{ .reg .u64 t; cvta.to.shared.u64 t, %1; cvt.u32.u64 %0, t; }" : "=r"(a) : "l"(p));
    return a;
}
__device__ __forceinline__ void cp16(uint32_t dst, const void* src) {
    asm volatile("cp.async.cg.shared.global [%0], [%1], 16;" :: "r"(dst), "l"(src) : "memory");
}
__device__ __forceinline__ void cp_commit() {
    asm volatile("cp.async.commit_group;" ::: "memory");
}
__device__ __forceinline__ void cp_wait2() {
    asm volatile("cp.async.wait_group 2;" ::: "memory");
}
__device__ __forceinline__ void mma16816(float* d, const uint32_t* a, const uint32_t* b) {
    asm volatile(
        "mma.sync.aligned.m16n8k16.row.col.f32.bf16.bf16.f32 "
        "{%0,%1,%2,%3}, {%4,%5,%6,%7}, {%8,%9}, {%0,%1,%2,%3};"
        : "+f"(d[0]), "+f"(d[1]), "+f"(d[2]), "+f"(d[3])
        : "r"(a[0]), "r"(a[1]), "r"(a[2]), "r"(a[3]), "r"(b[0]), "r"(b[1]));
}
__device__ __forceinline__ void mma16816h(float* d, const uint32_t* a, const uint32_t* b) {
    asm volatile(
        "mma.sync.aligned.m16n8k16.row.col.f32.f16.f16.f32 "
        "{%0,%1,%2,%3}, {%4,%5,%6,%7}, {%8,%9}, {%0,%1,%2,%3};"
        : "+f"(d[0]), "+f"(d[1]), "+f"(d[2]), "+f"(d[3])
        : "r"(a[0]), "r"(a[1]), "r"(a[2]), "r"(a[3]), "r"(b[0]), "r"(b[1]));
}
__device__ __forceinline__ uint32_t lds32(uint32_t addr) {
    uint32_t v;
    asm volatile("ld.shared.b32 %0, [%1];" : "=r"(v) : "r"(addr));
    return v;
}
__device__ __forceinline__ void lds64(uint32_t addr, uint32_t& a, uint32_t& b) {
    asm volatile("ld.shared.v2.b32 {%0,%1}, [%2];" : "=r"(a), "=r"(b) : "r"(addr));
}

// ============ activation split: fp32 -> fp16 hi/lo, K-permuted ============
__global__ __launch_bounds__(256) void split_h_kernel(
    const float4* __restrict__ in, __half2* __restrict__ hi,
    __half2* __restrict__ lo, int n4)
{
    const int i = blockIdx.x * blockDim.x + threadIdx.x;
    if (i >= n4) return;
    float4 v = in[i];
    __half2 h01 = __floats2half2_rn(v.x, v.y);
    __half2 h23 = __floats2half2_rn(v.z, v.w);
    float2 f01 = __half22float2(h01);
    float2 f23 = __half22float2(h23);
    __half2 l01 = __floats2half2_rn(v.x - f01.x, v.y - f01.y);
    __half2 l23 = __floats2half2_rn(v.z - f23.x, v.w - f23.y);
    // elems 4i..4i+3 ; group G = i>>2, j = i&3 ; pair positions per j: {0,2},{4,6},{1,3},{5,7}
    const int j = i & 3;
    const int base = (i >> 2) * 8;
    const int np0 = (j < 2) ? (4*j)     : (4*j - 7);
    const int np1 = (j < 2) ? (4*j + 2) : (4*j - 5);
    hi[base + np0] = h01; hi[base + np1] = h23;
    lo[base + np0] = l01; lo[base + np1] = l23;
}

// ============ weight transpose: single fp16, K-permuted half2 stores ============
__global__ __launch_bounds__(256) void split_t_h_kernel(
    const float* __restrict__ B, __half* __restrict__ th, int K, int N)
{
    __shared__ float tile[32][33];
    const int tx = threadIdx.x, ty = threadIdx.y;
    const int n0 = blockIdx.x * 32, k0 = blockIdx.y * 32;
#pragma unroll
    for (int j = ty; j < 32; j += 8)
        tile[j][tx] = B[(size_t)(k0 + j) * N + n0 + tx];
    __syncthreads();
    if (tx < 16) {
        const int P = tx & 7;
        const int kbase = k0 + ((tx >= 8) ? 16 : 0) + knp(P) * 2;
#pragma unroll
        for (int j = ty; j < 32; j += 8) {
            __half2 hv = __floats2half2_rn(tile[2*tx][j], tile[2*tx + 1][j]);
            *(__half2*)(th + (size_t)(n0 + j) * K + kbase) = hv;
        }
    }
}

// ============ fp16x2 GEMM: A split hi/lo (K-permuted), W single fp16 (K-permuted) ============
// mode 0: store fp32; 1: +R; 2: *2; 5: silu(R)*acc
#define BG_ROWB   96
#define BG_BUF    (128*BG_ROWB)
#define HG_STAGE  (3*BG_BUF)
#define HG_SMEM   (3*HG_STAGE)

__global__ __launch_bounds__(256, 2) void hgemm_kernel(
    const __half* __restrict__ Ahi, const __half* __restrict__ Alo,
    const __half* __restrict__ W,
    const float* __restrict__ R, float* __restrict__ Cf,
    __half* __restrict__ Chi, __half* __restrict__ Clo,
    int M, int N, int K, int ldc, int mode)
{
    extern __shared__ char sm_c[];
    const uint32_t smb = smem_u32(sm_c);

    const int tid = threadIdx.x;
    const int wid = tid >> 5;
    const int lane = tid & 31;
    const int bm = blockIdx.y * 128, bn = blockIdx.x * 128;
    const int m0 = (wid >> 2) * 64;
    const int n0 = (wid & 3) * 32;
    const int qrow = lane >> 2;
    const int q8 = (lane & 3) * 8;

    const int nch = K >> 5;

    auto issue_stage = [&](int t) {
        const int k0 = t * 32;
        const uint32_t sb = smb + (uint32_t)(t % 3) * HG_STAGE;
#pragma unroll
        for (int c = 0; c < 2; ++c) {
            const int idx = tid + c * 256;
            const int row = idx >> 2, q = idx & 3;
            const uint32_t so = (uint32_t)row * BG_ROWB + q * 16;
            const size_t goA = (size_t)(bm + row) * K + k0 + q * 8;
            const size_t goB = (size_t)(bn + row) * K + k0 + q * 8;
            cp16(sb + so,            Ahi + goA);
            cp16(sb + BG_BUF + so,   Alo + goA);
            cp16(sb + 2*BG_BUF + so, W + goB);
        }
        cp_commit();
    };

    issue_stage(0); issue_stage(1); issue_stage(2);

    float acc[4][4][4];
#pragma unroll
    for (int a = 0; a < 4; ++a)
#pragma unroll
        for (int b = 0; b < 4; ++b)
#pragma unroll
            for (int c = 0; c < 4; ++c) acc[a][b][c] = 0.f;

    for (int t = 0; t < nch; ++t) {
        cp_wait2();
        __syncthreads();
        const uint32_t Ah = smb + (uint32_t)(t % 3) * HG_STAGE;
        const uint32_t Al = Ah + BG_BUF;
        const uint32_t Bh = Ah + 2*BG_BUF;
#pragma unroll
        for (int kb = 0; kb <= 48; kb += 48) {       // two k16 steps: permuted 32B each -> +48? no:
            // NOTE: each k16 group = 32 bytes; row holds 2 groups at byte offsets 0 and 32.
            // kb iterates 0, 32.
            ;
        }
#pragma unroll
        for (int kb = 0; kb <= 32; kb += 32) {
            uint32_t ahi[4][4], alo[4][4], bh[4][2];
#pragma unroll
            for (int mt = 0; mt < 4; ++mt) {
                const uint32_t off = (uint32_t)(m0 + mt*16 + qrow) * BG_ROWB + kb + q8;
                lds64(Ah + off,            ahi[mt][0], ahi[mt][2]);
                lds64(Ah + off + 8*BG_ROWB, ahi[mt][1], ahi[mt][3]);
                lds64(Al + off,            alo[mt][0], alo[mt][2]);
                lds64(Al + off + 8*BG_ROWB, alo[mt][1], alo[mt][3]);
            }
#pragma unroll
            for (int nt = 0; nt < 4; ++nt) {
                const uint32_t off = (uint32_t)(n0 + nt*8 + qrow) * BG_ROWB + kb + q8;
                lds64(Bh + off, bh[nt][0], bh[nt][1]);
            }
#pragma unroll
            for (int mt = 0; mt < 4; ++mt)
#pragma unroll
                for (int nt = 0; nt < 4; ++nt) {
                    mma16816h(acc[mt][nt], ahi[mt], bh[nt]);
                    mma16816h(acc[mt][nt], alo[mt], bh[nt]);
                }
        }
        __syncthreads();
        if (t + 3 < nch) issue_stage(t + 3);
        else cp_commit();
    }

#pragma unroll
    for (int mt = 0; mt < 4; ++mt) {
        const int r0 = bm + m0 + mt*16 + qrow;
#pragma unroll
        for (int nt = 0; nt < 4; ++nt) {
            const int c = bn + n0 + nt*8 + (lane & 3) * 2;
            float2 v0 = make_float2(acc[mt][nt][0], acc[mt][nt][1]);
            float2 v1 = make_float2(acc[mt][nt][2], acc[mt][nt][3]);
            if (mode == 1) {
                const float* q0 = R + (size_t)r0 * ldc + c;
                const float* q1 = R + (size_t)(r0 + 8) * ldc + c;
                v0.x += q0[0]; v0.y += q0[1];
                v1.x += q1[0]; v1.y += q1[1];
            } else if (mode == 2) {
                v0.x *= 2.f; v0.y *= 2.f; v1.x *= 2.f; v1.y *= 2.f;
            } else if (mode == 5) {
                const float* q0 = R + (size_t)r0 * ldc + c;
                const float* q1 = R + (size_t)(r0 + 8) * ldc + c;
                const float s0 = q0[0], s1 = q0[1], s2 = q1[0], s3 = q1[1];
                v0.x *= s0 / (1.f + __expf(-s0));
                v0.y *= s1 / (1.f + __expf(-s1));
                v1.x *= s2 / (1.f + __expf(-s2));
                v1.y *= s3 / (1.f + __expf(-s3));
            }
            if (Cf) {
                *(float2*)(Cf + (size_t)r0 * ldc + c) = v0;
                *(float2*)(Cf + (size_t)(r0 + 8) * ldc + c) = v1;
            }
            if (Chi) {
                // permuted column for next-gemm K layout
                const int P = (nt & 1) * 4 + (lane & 3);
                const int c2 = bn + n0 + (nt >> 1) * 16 + knp(P) * 2;
                __half2 h0 = __floats2half2_rn(v0.x, v0.y);
                __half2 h1 = __floats2half2_rn(v1.x, v1.y);
                float2 f0 = __half22float2(h0);
                float2 f1 = __half22float2(h1);
                __half2 l0 = __floats2half2_rn(v0.x - f0.x, v0.y - f0.y);
                __half2 l1 = __floats2half2_rn(v1.x - f1.x, v1.y - f1.y);
                *(__half2*)(Chi + (size_t)r0 * ldc + c2) = h0;
                *(__half2*)(Chi + (size_t)(r0 + 8) * ldc + c2) = h1;
                *(__half2*)(Clo + (size_t)r0 * ldc + c2) = l0;
                *(__half2*)(Clo + (size_t)(r0 + 8) * ldc + c2) = l1;
            }
        }
    }
}

// ---------------- rmsnorm: optional fp32 out + fp16 hi/lo split (K-permuted) ----------------
__global__ __launch_bounds__(256) void rmsnorm_h_kernel(
    const float* __restrict__ x, const float* __restrict__ g,
    float* __restrict__ outf, __half2* __restrict__ hi, __half2* __restrict__ lo)
{
    __shared__ float red[8];
    __shared__ float sscale;
    const int row = blockIdx.x;
    const int t = threadIdx.x;
    const float4* xr = (const float4*)(x + (size_t)row * 1024);
    float4 v = xr[t];
    float ss = v.x*v.x + v.y*v.y + v.z*v.z + v.w*v.w;
#pragma unroll
    for (int o = 16; o; o >>= 1) ss += __shfl_xor_sync(0xffffffffu, ss, o);
    if ((t & 31) == 0) red[t >> 5] = ss;
    __syncthreads();
    if (t == 0) {
        float s = 0.f;
#pragma unroll
        for (int i = 0; i < 8; ++i) s += red[i];
        sscale = rsqrtf(s * (1.0f/1024.0f) + 1e-6f);
    }
    __syncthreads();
    const float sc = sscale;
    float4 gv = ((const float4*)g)[t];
    float4 o;
    o.x = v.x*sc*gv.x; o.y = v.y*sc*gv.y; o.z = v.z*sc*gv.z; o.w = v.w*sc*gv.w;
    if (outf) ((float4*)(outf + (size_t)row * 1024))[t] = o;
    __half2 h01 = __floats2half2_rn(o.x, o.y);
    __half2 h23 = __floats2half2_rn(o.z, o.w);
    float2 f01 = __half22float2(h01);
    float2 f23 = __half22float2(h23);
    __half2 l01 = __floats2half2_rn(o.x - f01.x, o.y - f01.y);
    __half2 l23 = __floats2half2_rn(o.z - f23.x, o.w - f23.y);
    const int j = t & 3;
    const size_t base = (size_t)row * 512 + (t >> 2) * 8;
    const int np0 = (j < 2) ? (4*j)     : (4*j - 7);
    const int np1 = (j < 2) ? (4*j + 2) : (4*j - 5);
    hi[base + np0] = h01; hi[base + np1] = h23;
    lo[base + np0] = l01; lo[base + np1] = l23;
}

// ---------------- lambda (both sets in one launch: 32 blocks) ----------------
__global__ void lambda2_kernel(
    const float* __restrict__ lq1s, const float* __restrict__ lk1s,
    const float* __restrict__ lq2s, const float* __restrict__ lk2s,
    const float* __restrict__ lq1c, const float* __restrict__ lk1c,
    const float* __restrict__ lq2c, const float* __restrict__ lk2c,
    float* __restrict__ lam)
{
    const int hb = blockIdx.x;
    const int h = hb & 15;
    const float* lq1 = (hb < 16) ? lq1s : lq1c;
    const float* lk1 = (hb < 16) ? lk1s : lk1c;
    const float* lq2 = (hb < 16) ? lq2s : lq2c;
    const float* lk2 = (hb < 16) ? lk2s : lk2c;
    const int lane = threadIdx.x;
    float s1 = 0.f, s2 = 0.f;
    for (int d = lane; d < 64; d += 32) {
        s1 += lq1[h*64 + d] * lk1[h*64 + d];
        s2 += lq2[h*64 + d] * lk2[h*64 + d];
    }
#pragma unroll
    for (int o = 16; o; o >>= 1) {
        s1 += __shfl_xor_sync(0xffffffffu, s1, o);
        s2 += __shfl_xor_sync(0xffffffffu, s2, o);
    }
    if (lane == 0) lam[hb] = expf(s1) - expf(s2) + 0.8f;
}

// ================ tensor-core flash diff-attention (bf16x3, fp16 split out) ================
#define FLM_ROWB 144u
#define SQ1H 0u
#define SQ2H 18432u
#define SK1H 36864u
#define SK2H 55296u
#define SVH  73728u
#define FLM_SMEM 92160
#define SOEX 36864u

__global__ __launch_bounds__(256, 2) void flash_mma_kernel(
    const float* __restrict__ Q, const float* __restrict__ Kg,
    const float* __restrict__ Vg, const float* __restrict__ lamp,
    __half* __restrict__ Ohi, __half* __restrict__ Olo,
    int Sq, int Sk, int causal, int ldr)
{
    extern __shared__ char smf[];
    const uint32_t smb = smem_u32(smf);
    const int tid = threadIdx.x, wid = tid >> 5, lane = tid & 31;
    const int g = lane >> 2, qq = lane & 3;
    const int qt = causal ? ((int)gridDim.x - 1 - (int)blockIdx.x) : (int)blockIdx.x;
    const int h = blockIdx.y, b = blockIdx.z;
    const int mat = wid >> 2;
    const int slab = (wid & 3) * 16;

#pragma unroll
    for (int u = 0; u < 8; ++u) {
        const int idx = tid + u * 256;
        const int r = idx >> 5, d0 = (idx & 31) * 4;
        const float4 v = *(const float4*)(Q + (size_t)(b*Sq + qt*64 + r) * ldr + h * 128 + d0);
        const uint32_t off = ((d0 < 64) ? SQ1H : SQ2H) + (uint32_t)r * FLM_ROWB + (uint32_t)(d0 & 63) * 2;
        __nv_bfloat162 h01 = __floats2bfloat162_rn(v.x, v.y);
        __nv_bfloat162 h23 = __floats2bfloat162_rn(v.z, v.w);
        float2 f01 = __bfloat1622float2(h01), f23 = __bfloat1622float2(h23);
        __nv_bfloat162 l01 = __floats2bfloat162_rn(v.x - f01.x, v.y - f01.y);
        __nv_bfloat162 l23 = __floats2bfloat162_rn(v.z - f23.x, v.w - f23.y);
        *(__nv_bfloat162*)(smf + off)        = h01;
        *(__nv_bfloat162*)(smf + off + 4)    = h23;
        *(__nv_bfloat162*)(smf + off + 9216) = l01;
        *(__nv_bfloat162*)(smf + off + 9220) = l23;
    }

    float O[8][4];
#pragma unroll
    for (int t = 0; t < 8; ++t)
#pragma unroll
        for (int c = 0; c < 4; ++c) O[t][c] = 0.f;
    float rm[2] = { -1e30f, -1e30f }, rl[2] = { 0.f, 0.f };

    const int nkt = causal ? (qt + 1) : (Sk >> 6);

    for (int kt = 0; kt < nkt; ++kt) {
        __syncthreads();
#pragma unroll
        for (int u = 0; u < 8; ++u) {
            const int idx = tid + u * 256;
            const int r = idx >> 5, d0 = (idx & 31) * 4;
            const float4 v = *(const float4*)(Kg + (size_t)(b*Sk + kt*64 + r) * ldr + h * 128 + d0);
            const uint32_t off = ((d0 < 64) ? SK1H : SK2H) + (uint32_t)r * FLM_ROWB + (uint32_t)(d0 & 63) * 2;
            __nv_bfloat162 h01 = __floats2bfloat162_rn(v.x, v.y);
            __nv_bfloat162 h23 = __floats2bfloat162_rn(v.z, v.w);
            float2 f01 = __bfloat1622float2(h01), f23 = __bfloat1622float2(h23);
            __nv_bfloat162 l01 = __floats2bfloat162_rn(v.x - f01.x, v.y - f01.y);
            __nv_bfloat162 l23 = __floats2bfloat162_rn(v.z - f23.x, v.w - f23.y);
            *(__nv_bfloat162*)(smf + off)        = h01;
            *(__nv_bfloat162*)(smf + off + 4)    = h23;
            *(__nv_bfloat162*)(smf + off + 9216) = l01;
            *(__nv_bfloat162*)(smf + off + 9220) = l23;
        }
#pragma unroll
        for (int u = 0; u < 4; ++u) {
            const int idx = tid + u * 256;
            const int key = idx >> 4, d0 = (idx & 15) * 4;
            const float4 v = *(const float4*)(Vg + (size_t)(b*Sk + kt*64 + key) * ldr + h * 64 + d0);
            const float vv[4] = { v.x, v.y, v.z, v.w };
#pragma unroll
            for (int j = 0; j < 4; ++j) {
                const float f = vv[j];
                __nv_bfloat16 hb = __float2bfloat16(f);
                __nv_bfloat16 lb = __float2bfloat16(f - __bfloat162float(hb));
                const uint32_t o2 = (uint32_t)(d0 + j) * FLM_ROWB + (uint32_t)key * 2;
                *(__nv_bfloat16*)(smf + SVH + o2) = hb;
                *(__nv_bfloat16*)(smf + SVH + 9216 + o2) = lb;
            }
        }
        __syncthreads();

        float S[8][4];
#pragma unroll
        for (int t = 0; t < 8; ++t)
#pragma unroll
            for (int c = 0; c < 4; ++c) S[t][c] = 0.f;

        const uint32_t qB = smb + (mat ? SQ2H : SQ1H);
        const uint32_t kB = smb + (mat ? SK2H : SK1H);
#pragma unroll
        for (int s = 0; s < 4; ++s) {
            uint32_t ah[4], al[4];
            const uint32_t ao = qB + (uint32_t)(slab + g) * FLM_ROWB + s * 32 + qq * 4;
            ah[0] = lds32(ao);              ah[1] = lds32(ao + 8*FLM_ROWB);
            ah[2] = lds32(ao + 16);         ah[3] = lds32(ao + 8*FLM_ROWB + 16);
            al[0] = lds32(ao + 9216);       al[1] = lds32(ao + 9216 + 8*FLM_ROWB);
            al[2] = lds32(ao + 9216 + 16);  al[3] = lds32(ao + 9216 + 8*FLM_ROWB + 16);
#pragma unroll
            for (int nt = 0; nt < 8; ++nt) {
                const uint32_t bo = kB + (uint32_t)(nt*8 + g) * FLM_ROWB + s * 32 + qq * 4;
                uint32_t bh[2], bl[2];
                bh[0] = lds32(bo);        bh[1] = lds32(bo + 16);
                bl[0] = lds32(bo + 9216); bl[1] = lds32(bo + 9216 + 16);
                mma16816(S[nt], ah, bh);
                mma16816(S[nt], ah, bl);
                mma16816(S[nt], al, bh);
            }
        }

        const bool dg = (causal != 0) && (kt == qt);
        uint32_t pH[8][2], pL[8][2];
#pragma unroll
        for (int j = 0; j < 2; ++j) {
            const int rloc = slab + g + j*8;
            float mx = -1e30f;
#pragma unroll
            for (int t = 0; t < 8; ++t) {
                float* sp = &S[t][j*2];
                sp[0] *= 0.125f; sp[1] *= 0.125f;
                if (dg) {
                    const int c = t*8 + qq*2;
                    if (c > rloc)     sp[0] = -1e9f;
                    if (c + 1 > rloc) sp[1] = -1e9f;
                }
                mx = fmaxf(mx, fmaxf(sp[0], sp[1]));
            }
            mx = fmaxf(mx, __shfl_xor_sync(0xffffffffu, mx, 1));
            mx = fmaxf(mx, __shfl_xor_sync(0xffffffffu, mx, 2));
            const float mn = fmaxf(rm[j], mx);
            const float alw = __expf(rm[j] - mn);
            rm[j] = mn;
            float rs = 0.f;
#pragma unroll
            for (int t = 0; t < 8; ++t) {
                const float p0 = __expf(S[t][j*2]   - mn);
                const float p1 = __expf(S[t][j*2+1] - mn);
                rs += p0 + p1;
                __nv_bfloat162 hp = __floats2bfloat162_rn(p0, p1);
                float2 fp = __bfloat1622float2(hp);
                __nv_bfloat162 lp = __floats2bfloat162_rn(p0 - fp.x, p1 - fp.y);
                pH[t][j] = *(uint32_t*)&hp;
                pL[t][j] = *(uint32_t*)&lp;
            }
            rs += __shfl_xor_sync(0xffffffffu, rs, 1);
            rs += __shfl_xor_sync(0xffffffffu, rs, 2);
            rl[j] = rl[j] * alw + rs;
#pragma unroll
            for (int t = 0; t < 8; ++t) { O[t][j*2] *= alw; O[t][j*2+1] *= alw; }
        }

#pragma unroll
        for (int s = 0; s < 4; ++s) {
            const uint32_t aP[4]  = { pH[2*s][0], pH[2*s][1], pH[2*s+1][0], pH[2*s+1][1] };
            const uint32_t aPl[4] = { pL[2*s][0], pL[2*s][1], pL[2*s+1][0], pL[2*s+1][1] };
#pragma unroll
            for (int nt = 0; nt < 8; ++nt) {
                const uint32_t bo = smb + SVH + (uint32_t)(nt*8 + g) * FLM_ROWB + s * 32 + qq * 4;
                uint32_t bh[2], bl[2];
                bh[0] = lds32(bo);        bh[1] = lds32(bo + 16);
                bl[0] = lds32(bo + 9216); bl[1] = lds32(bo + 9216 + 16);
                mma16816(O[nt], aP,  bh);
                mma16816(O[nt], aP,  bl);
                mma16816(O[nt], aPl, bh);
            }
        }
    }

    __syncthreads();
    if (mat == 1) {
#pragma unroll
        for (int j = 0; j < 2; ++j) {
            const float inv = 1.f / rl[j];
            const int row = slab + g + j*8;
#pragma unroll
            for (int t = 0; t < 8; ++t) {
                const int col = t*8 + qq*2;
                float2 w = make_float2(O[t][j*2] * inv, O[t][j*2+1] * inv);
                *(float2*)(smf + SOEX + ((uint32_t)row * 68 + col) * 4) = w;
            }
        }
    }
    __syncthreads();
    if (mat == 0) {
        const float lam = lamp[h];
#pragma unroll
        for (int j = 0; j < 2; ++j) {
            const float inv = 1.f / rl[j];
            const int row = slab + g + j*8;
            float vbuf[16];
            float ss = 0.f;
#pragma unroll
            for (int t = 0; t < 8; ++t) {
                const int col = t*8 + qq*2;
                const float2 w = *(const float2*)(smf + SOEX + ((uint32_t)row * 68 + col) * 4);
                const float v0 = O[t][j*2]   * inv - lam * w.x;
                const float v1 = O[t][j*2+1] * inv - lam * w.y;
                vbuf[2*t] = v0; vbuf[2*t+1] = v1;
                ss += v0*v0 + v1*v1;
            }
            ss += __shfl_xor_sync(0xffffffffu, ss, 1);
            ss += __shfl_xor_sync(0xffffffffu, ss, 2);
            const float scl = rsqrtf(ss * (1.0f/64.0f) + 1e-6f) * 0.2f;
            const size_t ob = ((size_t)(b*Sq + qt*64 + row) * Hh + h) * 64;
#pragma unroll
            for (int t = 0; t < 8; ++t) {
                // K-permuted output column (feeds hgemm A)
                const int P = (t & 1) * 4 + qq;
                const int col2 = (t >> 1) * 16 + knp(P) * 2;
                const float v0 = vbuf[2*t] * scl, v1 = vbuf[2*t+1] * scl;
                __half2 hh = __floats2half2_rn(v0, v1);
                float2 fh = __half22float2(hh);
                __half2 ll = __floats2half2_rn(v0 - fh.x, v1 - fh.y);
                *(__half2*)(Ohi + ob + col2) = hh;
                *(__half2*)(Olo + ob + col2) = ll;
            }
        }
    }
}

// ---------------- host-side launch helpers ----------------
static __half *s_wh, *s_ahi, *s_alo, *s_bhi, *s_blo;

static void splitWh(const float* W, uint32_t off, int K, int N) {
    split_t_h_kernel<<<dim3(N/32, K/32), dim3(32, 8)>>>(W, s_wh + off, K, N);
}
static void hgemm(const __half* ahi, const __half* alo, uint32_t woff,
                  const float* R, float* Cf, __half* chi, __half* clo,
                  int M, int N, int K, int ldc, int mode)
{
    dim3 grid(N / 128, M / 128);
    hgemm_kernel<<<grid, 256, HG_SMEM>>>(ahi, alo, s_wh + woff,
                                         R, Cf, chi, clo, M, N, K, ldc, mode);
}

extern "C" void kernel_launch(void* const* d_in, const int* in_sizes, int n_in,
                              void* d_out, int out_size)
{
    const float* x    = (const float*)d_in[0];
    const float* enc  = (const float*)d_in[1];
    const float* Wq_s = (const float*)d_in[2];
    const float* Wk_s = (const float*)d_in[3];
    const float* Wv_s = (const float*)d_in[4];
    const float* Wo_s = (const float*)d_in[5];
    const float* lq1s = (const float*)d_in[6];
    const float* lk1s = (const float*)d_in[7];
    const float* lq2s = (const float*)d_in[8];
    const float* lk2s = (const float*)d_in[9];
    const float* Wq_c = (const float*)d_in[10];
    const float* Wk_c = (const float*)d_in[11];
    const float* Wv_c = (const float*)d_in[12];
    const float* Wo_c = (const float*)d_in[13];
    const float* lq1c = (const float*)d_in[14];
    const float* lk1c = (const float*)d_in[15];
    const float* lq2c = (const float*)d_in[16];
    const float* lk2c = (const float*)d_in[17];
    const float* grms = (const float*)d_in[18];
    const float* W1   = (const float*)d_in[19];
    const float* W2   = (const float*)d_in[20];
    const float* W3   = (const float*)d_in[21];
    float* out = (float*)d_out;

    float *hn, *qkv, *h2, *m1, *lam;
    cudaGetSymbolAddress((void**)&hn,  g_hn);
    cudaGetSymbolAddress((void**)&qkv, g_qkv);
    cudaGetSymbolAddress((void**)&h2,  g_h2);
    cudaGetSymbolAddress((void**)&m1,  g_m1);
    cudaGetSymbolAddress((void**)&lam, g_lam);
    cudaGetSymbolAddress((void**)&s_wh,  g_wh);
    cudaGetSymbolAddress((void**)&s_ahi, g_ahi);
    cudaGetSymbolAddress((void**)&s_alo, g_alo);
    cudaGetSymbolAddress((void**)&s_bhi, g_bhi);
    cudaGetSymbolAddress((void**)&s_blo, g_blo);

    cudaFuncSetAttribute(flash_mma_kernel,
                         cudaFuncAttributeMaxDynamicSharedMemorySize, FLM_SMEM);
    cudaFuncSetAttribute(hgemm_kernel,
                         cudaFuncAttributeMaxDynamicSharedMemorySize, HG_SMEM);

    // ---- weight prep: single fp16 transposed, K-permuted ----
    splitWh(Wq_s, OW_QS, 1024, 2048);
    splitWh(Wk_s, OW_KS, 1024, 2048);
    splitWh(Wv_s, OW_VS, 1024, 1024);
    splitWh(Wo_s, OW_OS, 1024, 1024);
    splitWh(Wq_c, OW_QC, 1024, 2048);
    splitWh(Wk_c, OW_KC, 1024, 2048);
    splitWh(Wv_c, OW_VC, 1024, 1024);
    splitWh(Wo_c, OW_OC, 1024, 1024);
    splitWh(W1,   OW_W1, 1024, 4096);
    splitWh(W2,   OW_W2, 1024, 4096);
    splitWh(W3,   OW_W3, 4096, 1024);

    lambda2_kernel<<<32, 32>>>(lq1s, lk1s, lq2s, lk2s, lq1c, lk1c, lq2c, lk2c, lam);

    // h = rmsnorm(x, g) -> fp32 hn (residual) + fp16 split in A (K-permuted)
    rmsnorm_h_kernel<<<ROWS, 256>>>(x, grms, hn, (__half2*)s_ahi, (__half2*)s_alo);

    // ---- self diff-attention (causal): merged QKV GEMM (N=5120) ----
    hgemm(s_ahi, s_alo, OW_QS, nullptr, qkv, nullptr, nullptr, ROWS, 5120, 1024, 5120, 0);
    flash_mma_kernel<<<dim3(Tt/64, Hh, Bb), 256, FLM_SMEM>>>(qkv, qkv + 2048, qkv + 4096,
        lam, s_bhi, s_blo, Tt, Tt, 1, 5120);
    // h1 = ao @ Wo_s + hn  -> fp16 split into A (K-permuted)
    hgemm(s_bhi, s_blo, OW_OS, hn, nullptr, s_ahi, s_alo, ROWS, 1024, 1024, 1024, 1);

    // ---- cross diff-attention (not causal) ----
    hgemm(s_ahi, s_alo, OW_QC, nullptr, qkv, nullptr, nullptr, ROWS, 2048, 1024, 5120, 0);
    split_h_kernel<<<(ROWS*1024/4)/256, 256>>>((const float4*)enc,
        (__half2*)s_bhi, (__half2*)s_blo, ROWS*1024/4);
    hgemm(s_bhi, s_blo, OW_KC, nullptr, qkv + 2048, nullptr, nullptr, ROWS, 3072, 1024, 5120, 0);
    flash_mma_kernel<<<dim3(Tt/64, Hh, Bb), 256, FLM_SMEM>>>(qkv, qkv + 2048, qkv + 4096,
        lam + 16, s_ahi, s_alo, Tt, Tt, 0, 5120);
    // h2 = 2 * (ao @ Wo_c) -> fp32 (residual + rmsnorm input)
    hgemm(s_ahi, s_alo, OW_OC, nullptr, h2, nullptr, nullptr, ROWS, 1024, 1024, 1024, 2);

    // ---- MLP (fp16 2-term path) ----
    rmsnorm_h_kernel<<<ROWS, 256>>>(h2, grms, nullptr, (__half2*)s_bhi, (__half2*)s_blo);
    hgemm(s_bhi, s_blo, OW_W1, nullptr, m1, nullptr, nullptr, ROWS, DFF, 1024, DFF, 0);
    hgemm(s_bhi, s_blo, OW_W2, m1, nullptr, s_ahi, s_alo, ROWS, DFF, 1024, DFF, 5);
    hgemm(s_ahi, s_alo, OW_W3, h2, out, nullptr, nullptr, ROWS, 1024, DFF, 1024, 1);
}

// round 16
// speedup vs baseline: 1.0160x; 1.0160x over previous
#include <cuda_runtime.h>
#include <cuda_bf16.h>
#include <cuda_fp16.h>
#include <math.h>
#include <stdint.h>

// ---------------- problem dims (fixed) ----------------
#define Bb   4
#define Tt   1024
#define Dd   1024
#define Hh   16
#define HSs  64
#define DFF  4096
#define ROWS (Bb*Tt)      // 4096

// ---------------- scratch (device globals; no allocs allowed) ----------------
__device__ float g_hn [ROWS*Dd];
__device__ float g_qkv[ROWS*5120];     // q(2048) | k(2048) | v(1024), row stride 5120
__device__ float g_h2 [ROWS*Dd];
__device__ float g_m1 [ROWS*DFF];
__device__ float g_lam[32];

// fp16 activation split buffers
#define NA_TOT (ROWS*DFF)
__device__ __half g_ahi[NA_TOT];
__device__ __half g_alo[NA_TOT];
__device__ __half g_bhi[NA_TOT];
__device__ __half g_blo[NA_TOT];

// fp16 weights (single term), transposed [N][K]
#define NHW_TOT (24u*1024u*1024u)
__device__ __half g_wh[NHW_TOT];
#define OW_QS (0u)
#define OW_KS (2u*1024u*1024u)
#define OW_VS (4u*1024u*1024u)
#define OW_OS (5u*1024u*1024u)
#define OW_QC (6u*1024u*1024u)
#define OW_KC (8u*1024u*1024u)
#define OW_VC (10u*1024u*1024u)
#define OW_OC (11u*1024u*1024u)
#define OW_W1 (12u*1024u*1024u)
#define OW_W2 (16u*1024u*1024u)
#define OW_W3 (20u*1024u*1024u)

// ================= small helpers =================
__device__ __forceinline__ uint32_t smem_u32(const void* p) {
    uint32_t a;
    asm("{ .reg .u64 t; cvta.to.shared.u64 t, %1; cvt.u32.u64 %0, t; }" : "=r"(a) : "l"(p));
    return a;
}
__device__ __forceinline__ void cp16(uint32_t dst, const void* src) {
    asm volatile("cp.async.cg.shared.global [%0], [%1], 16;" :: "r"(dst), "l"(src) : "memory");
}
__device__ __forceinline__ void cp_commit() {
    asm volatile("cp.async.commit_group;" ::: "memory");
}
__device__ __forceinline__ void cp_wait2() {
    asm volatile("cp.async.wait_group 2;" ::: "memory");
}
__device__ __forceinline__ void mma16816(float* d, const uint32_t* a, const uint32_t* b) {
    asm volatile(
        "mma.sync.aligned.m16n8k16.row.col.f32.bf16.bf16.f32 "
        "{%0,%1,%2,%3}, {%4,%5,%6,%7}, {%8,%9}, {%0,%1,%2,%3};"
        : "+f"(d[0]), "+f"(d[1]), "+f"(d[2]), "+f"(d[3])
        : "r"(a[0]), "r"(a[1]), "r"(a[2]), "r"(a[3]), "r"(b[0]), "r"(b[1]));
}
__device__ __forceinline__ void mma16816h(float* d, const uint32_t* a, const uint32_t* b) {
    asm volatile(
        "mma.sync.aligned.m16n8k16.row.col.f32.f16.f16.f32 "
        "{%0,%1,%2,%3}, {%4,%5,%6,%7}, {%8,%9}, {%0,%1,%2,%3};"
        : "+f"(d[0]), "+f"(d[1]), "+f"(d[2]), "+f"(d[3])
        : "r"(a[0]), "r"(a[1]), "r"(a[2]), "r"(a[3]), "r"(b[0]), "r"(b[1]));
}
__device__ __forceinline__ uint32_t lds32(uint32_t addr) {
    uint32_t v;
    asm volatile("ld.shared.b32 %0, [%1];" : "=r"(v) : "r"(addr));
    return v;
}

// ============ activation split: fp32 -> fp16 hi + fp16 lo ============
__global__ __launch_bounds__(256) void split_h_kernel(
    const float4* __restrict__ in, __half2* __restrict__ hi,
    __half2* __restrict__ lo, int n4)
{
    const int i = blockIdx.x * blockDim.x + threadIdx.x;
    if (i >= n4) return;
    float4 v = in[i];
    __half2 h01 = __floats2half2_rn(v.x, v.y);
    __half2 h23 = __floats2half2_rn(v.z, v.w);
    float2 f01 = __half22float2(h01);
    float2 f23 = __half22float2(h23);
    __half2 l01 = __floats2half2_rn(v.x - f01.x, v.y - f01.y);
    __half2 l23 = __floats2half2_rn(v.z - f23.x, v.w - f23.y);
    hi[2*i] = h01; hi[2*i+1] = h23;
    lo[2*i] = l01; lo[2*i+1] = l23;
}

// ============ merged weight transpose: ALL 11 weights in one launch ============
// Each 32x32 tile-block transposes W[K][N] fp32 -> th[N][K] fp16.
struct WDesc { const float* W; unsigned off; int K; int N; int start; };
struct WPack { WDesc d[11]; };

__global__ __launch_bounds__(256) void split_all_kernel(WPack p, __half* __restrict__ th)
{
    __shared__ float tile[32][33];
    const int id = blockIdx.x;
    int i = 0;
#pragma unroll
    for (int j = 1; j < 11; ++j) if (id >= p.d[j].start) i = j;
    const WDesc d = p.d[i];
    const int local = id - d.start;
    const int nx = d.N >> 5;
    const int n0 = (local % nx) * 32;
    const int k0 = (local / nx) * 32;
    __half* out = th + d.off;

    const int tx = threadIdx.x, ty = threadIdx.y;
#pragma unroll
    for (int j = ty; j < 32; j += 8)
        tile[j][tx] = d.W[(size_t)(k0 + j) * d.N + n0 + tx];
    __syncthreads();
    if (tx < 16) {
#pragma unroll
        for (int j = ty; j < 32; j += 8) {
            __half2 hv = __floats2half2_rn(tile[2*tx][j], tile[2*tx + 1][j]);
            *(__half2*)(out + (size_t)(n0 + j) * d.K + k0 + 2*tx) = hv;
        }
    }
}

// ============ fp16x2 GEMM: A split hi/lo, W single fp16 ============
// mode 0: store fp32; 1: +R; 2: *2; 5: silu(R)*acc
// C row stride = ldc (also used for R); split outputs dense with stride ldc.
#define BG_ROWB   80
#define BG_BUF    (128*BG_ROWB)
#define HG_STAGE  (3*BG_BUF)
#define HG_SMEM   (3*HG_STAGE)

__global__ __launch_bounds__(256, 2) void hgemm_kernel(
    const __half* __restrict__ Ahi, const __half* __restrict__ Alo,
    const __half* __restrict__ W,
    const float* __restrict__ R, float* __restrict__ Cf,
    __half* __restrict__ Chi, __half* __restrict__ Clo,
    int M, int N, int K, int ldc, int mode)
{
    extern __shared__ char sm_c[];
    const uint32_t smb = smem_u32(sm_c);

    const int tid = threadIdx.x;
    const int wid = tid >> 5;
    const int lane = tid & 31;
    const int bm = blockIdx.y * 128, bn = blockIdx.x * 128;
    const int m0 = (wid >> 2) * 64;
    const int n0 = (wid & 3) * 32;
    const int qrow = lane >> 2;
    const int qk4 = (lane & 3) * 4;

    const int nch = K >> 5;

    auto issue_stage = [&](int t) {
        const int k0 = t * 32;
        const uint32_t sb = smb + (uint32_t)(t % 3) * HG_STAGE;
#pragma unroll
        for (int c = 0; c < 2; ++c) {
            const int idx = tid + c * 256;
            const int row = idx >> 2, q = idx & 3;
            const uint32_t so = (uint32_t)row * BG_ROWB + q * 16;
            const size_t goA = (size_t)(bm + row) * K + k0 + q * 8;
            const size_t goB = (size_t)(bn + row) * K + k0 + q * 8;
            cp16(sb + so,            Ahi + goA);
            cp16(sb + BG_BUF + so,   Alo + goA);
            cp16(sb + 2*BG_BUF + so, W + goB);
        }
        cp_commit();
    };

    issue_stage(0); issue_stage(1); issue_stage(2);

    float acc[4][4][4];
#pragma unroll
    for (int a = 0; a < 4; ++a)
#pragma unroll
        for (int b = 0; b < 4; ++b)
#pragma unroll
            for (int c = 0; c < 4; ++c) acc[a][b][c] = 0.f;

    for (int t = 0; t < nch; ++t) {
        cp_wait2();
        __syncthreads();
        const char* Ah = sm_c + (t % 3) * HG_STAGE;
        const char* Al = Ah + BG_BUF;
        const char* Bh = Ah + 2*BG_BUF;
#pragma unroll
        for (int kb = 0; kb <= 32; kb += 32) {
            uint32_t ahi[4][4], alo[4][4], bh[4][2];
#pragma unroll
            for (int mt = 0; mt < 4; ++mt) {
                const uint32_t off = (uint32_t)(m0 + mt*16 + qrow) * BG_ROWB + kb + qk4;
                ahi[mt][0] = *(const uint32_t*)(Ah + off);
                ahi[mt][1] = *(const uint32_t*)(Ah + off + 8*BG_ROWB);
                ahi[mt][2] = *(const uint32_t*)(Ah + off + 16);
                ahi[mt][3] = *(const uint32_t*)(Ah + off + 8*BG_ROWB + 16);
                alo[mt][0] = *(const uint32_t*)(Al + off);
                alo[mt][1] = *(const uint32_t*)(Al + off + 8*BG_ROWB);
                alo[mt][2] = *(const uint32_t*)(Al + off + 16);
                alo[mt][3] = *(const uint32_t*)(Al + off + 8*BG_ROWB + 16);
            }
#pragma unroll
            for (int nt = 0; nt < 4; ++nt) {
                const uint32_t off = (uint32_t)(n0 + nt*8 + qrow) * BG_ROWB + kb + qk4;
                bh[nt][0] = *(const uint32_t*)(Bh + off);
                bh[nt][1] = *(const uint32_t*)(Bh + off + 16);
            }
#pragma unroll
            for (int mt = 0; mt < 4; ++mt)
#pragma unroll
                for (int nt = 0; nt < 4; ++nt) {
                    mma16816h(acc[mt][nt], ahi[mt], bh[nt]);
                    mma16816h(acc[mt][nt], alo[mt], bh[nt]);
                }
        }
        __syncthreads();
        if (t + 3 < nch) issue_stage(t + 3);
        else cp_commit();
    }

#pragma unroll
    for (int mt = 0; mt < 4; ++mt) {
        const int r0 = bm + m0 + mt*16 + qrow;
#pragma unroll
        for (int nt = 0; nt < 4; ++nt) {
            const int c = bn + n0 + nt*8 + (lane & 3) * 2;
            float2 v0 = make_float2(acc[mt][nt][0], acc[mt][nt][1]);
            float2 v1 = make_float2(acc[mt][nt][2], acc[mt][nt][3]);
            if (mode == 1) {
                const float* q0 = R + (size_t)r0 * ldc + c;
                const float* q1 = R + (size_t)(r0 + 8) * ldc + c;
                v0.x += q0[0]; v0.y += q0[1];
                v1.x += q1[0]; v1.y += q1[1];
            } else if (mode == 2) {
                v0.x *= 2.f; v0.y *= 2.f; v1.x *= 2.f; v1.y *= 2.f;
            } else if (mode == 5) {
                const float* q0 = R + (size_t)r0 * ldc + c;
                const float* q1 = R + (size_t)(r0 + 8) * ldc + c;
                const float s0 = q0[0], s1 = q0[1], s2 = q1[0], s3 = q1[1];
                v0.x *= s0 / (1.f + __expf(-s0));
                v0.y *= s1 / (1.f + __expf(-s1));
                v1.x *= s2 / (1.f + __expf(-s2));
                v1.y *= s3 / (1.f + __expf(-s3));
            }
            if (Cf) {
                *(float2*)(Cf + (size_t)r0 * ldc + c) = v0;
                *(float2*)(Cf + (size_t)(r0 + 8) * ldc + c) = v1;
            }
            if (Chi) {
                __half2 h0 = __floats2half2_rn(v0.x, v0.y);
                __half2 h1 = __floats2half2_rn(v1.x, v1.y);
                float2 f0 = __half22float2(h0);
                float2 f1 = __half22float2(h1);
                __half2 l0 = __floats2half2_rn(v0.x - f0.x, v0.y - f0.y);
                __half2 l1 = __floats2half2_rn(v1.x - f1.x, v1.y - f1.y);
                *(__half2*)(Chi + (size_t)r0 * ldc + c) = h0;
                *(__half2*)(Chi + (size_t)(r0 + 8) * ldc + c) = h1;
                *(__half2*)(Clo + (size_t)r0 * ldc + c) = l0;
                *(__half2*)(Clo + (size_t)(r0 + 8) * ldc + c) = l1;
            }
        }
    }
}

// ---------------- rmsnorm: optional fp32 out + fp16 hi/lo split ----------------
__global__ __launch_bounds__(256) void rmsnorm_h_kernel(
    const float* __restrict__ x, const float* __restrict__ g,
    float* __restrict__ outf, __half2* __restrict__ hi, __half2* __restrict__ lo)
{
    __shared__ float red[8];
    __shared__ float sscale;
    const int row = blockIdx.x;
    const int t = threadIdx.x;
    const float4* xr = (const float4*)(x + (size_t)row * 1024);
    float4 v = xr[t];
    float ss = v.x*v.x + v.y*v.y + v.z*v.z + v.w*v.w;
#pragma unroll
    for (int o = 16; o; o >>= 1) ss += __shfl_xor_sync(0xffffffffu, ss, o);
    if ((t & 31) == 0) red[t >> 5] = ss;
    __syncthreads();
    if (t == 0) {
        float s = 0.f;
#pragma unroll
        for (int i = 0; i < 8; ++i) s += red[i];
        sscale = rsqrtf(s * (1.0f/1024.0f) + 1e-6f);
    }
    __syncthreads();
    const float sc = sscale;
    float4 gv = ((const float4*)g)[t];
    float4 o;
    o.x = v.x*sc*gv.x; o.y = v.y*sc*gv.y; o.z = v.z*sc*gv.z; o.w = v.w*sc*gv.w;
    if (outf) ((float4*)(outf + (size_t)row * 1024))[t] = o;
    __half2 h01 = __floats2half2_rn(o.x, o.y);
    __half2 h23 = __floats2half2_rn(o.z, o.w);
    float2 f01 = __half22float2(h01);
    float2 f23 = __half22float2(h23);
    __half2 l01 = __floats2half2_rn(o.x - f01.x, o.y - f01.y);
    __half2 l23 = __floats2half2_rn(o.z - f23.x, o.w - f23.y);
    const size_t p = (size_t)row * 512 + t * 2;
    hi[p] = h01; hi[p+1] = h23;
    lo[p] = l01; lo[p+1] = l23;
}

// ---------------- lambda (both sets in one launch: 32 blocks) ----------------
__global__ void lambda2_kernel(
    const float* __restrict__ lq1s, const float* __restrict__ lk1s,
    const float* __restrict__ lq2s, const float* __restrict__ lk2s,
    const float* __restrict__ lq1c, const float* __restrict__ lk1c,
    const float* __restrict__ lq2c, const float* __restrict__ lk2c,
    float* __restrict__ lam)
{
    const int hb = blockIdx.x;
    const int h = hb & 15;
    const float* lq1 = (hb < 16) ? lq1s : lq1c;
    const float* lk1 = (hb < 16) ? lk1s : lk1c;
    const float* lq2 = (hb < 16) ? lq2s : lq2c;
    const float* lk2 = (hb < 16) ? lk2s : lk2c;
    const int lane = threadIdx.x;
    float s1 = 0.f, s2 = 0.f;
    for (int d = lane; d < 64; d += 32) {
        s1 += lq1[h*64 + d] * lk1[h*64 + d];
        s2 += lq2[h*64 + d] * lk2[h*64 + d];
    }
#pragma unroll
    for (int o = 16; o; o >>= 1) {
        s1 += __shfl_xor_sync(0xffffffffu, s1, o);
        s2 += __shfl_xor_sync(0xffffffffu, s2, o);
    }
    if (lane == 0) lam[hb] = expf(s1) - expf(s2) + 0.8f;
}

// ================ tensor-core flash diff-attention (bf16x3, fp16 split out) ================
// Q/K/V read from strided qkv buffer (row stride ldr floats)
#define FLM_ROWB 144u
#define SQ1H 0u
#define SQ2H 18432u
#define SK1H 36864u
#define SK2H 55296u
#define SVH  73728u
#define FLM_SMEM 92160
#define SOEX 36864u

__global__ __launch_bounds__(256, 2) void flash_mma_kernel(
    const float* __restrict__ Q, const float* __restrict__ Kg,
    const float* __restrict__ Vg, const float* __restrict__ lamp,
    __half* __restrict__ Ohi, __half* __restrict__ Olo,
    int Sq, int Sk, int causal, int ldr)
{
    extern __shared__ char smf[];
    const uint32_t smb = smem_u32(smf);
    const int tid = threadIdx.x, wid = tid >> 5, lane = tid & 31;
    const int g = lane >> 2, qq = lane & 3;
    // LPT scheduling: causal work grows with qt, so launch heavy tiles first
    const int qt = causal ? ((int)gridDim.x - 1 - (int)blockIdx.x) : (int)blockIdx.x;
    const int h = blockIdx.y, b = blockIdx.z;
    const int mat = wid >> 2;
    const int slab = (wid & 3) * 16;

#pragma unroll
    for (int u = 0; u < 8; ++u) {
        const int idx = tid + u * 256;
        const int r = idx >> 5, d0 = (idx & 31) * 4;
        const float4 v = *(const float4*)(Q + (size_t)(b*Sq + qt*64 + r) * ldr + h * 128 + d0);
        const uint32_t off = ((d0 < 64) ? SQ1H : SQ2H) + (uint32_t)r * FLM_ROWB + (uint32_t)(d0 & 63) * 2;
        __nv_bfloat162 h01 = __floats2bfloat162_rn(v.x, v.y);
        __nv_bfloat162 h23 = __floats2bfloat162_rn(v.z, v.w);
        float2 f01 = __bfloat1622float2(h01), f23 = __bfloat1622float2(h23);
        __nv_bfloat162 l01 = __floats2bfloat162_rn(v.x - f01.x, v.y - f01.y);
        __nv_bfloat162 l23 = __floats2bfloat162_rn(v.z - f23.x, v.w - f23.y);
        *(__nv_bfloat162*)(smf + off)        = h01;
        *(__nv_bfloat162*)(smf + off + 4)    = h23;
        *(__nv_bfloat162*)(smf + off + 9216) = l01;
        *(__nv_bfloat162*)(smf + off + 9220) = l23;
    }

    float O[8][4];
#pragma unroll
    for (int t = 0; t < 8; ++t)
#pragma unroll
        for (int c = 0; c < 4; ++c) O[t][c] = 0.f;
    float rm[2] = { -1e30f, -1e30f }, rl[2] = { 0.f, 0.f };

    const int nkt = causal ? (qt + 1) : (Sk >> 6);

    for (int kt = 0; kt < nkt; ++kt) {
        __syncthreads();
#pragma unroll
        for (int u = 0; u < 8; ++u) {
            const int idx = tid + u * 256;
            const int r = idx >> 5, d0 = (idx & 31) * 4;
            const float4 v = *(const float4*)(Kg + (size_t)(b*Sk + kt*64 + r) * ldr + h * 128 + d0);
            const uint32_t off = ((d0 < 64) ? SK1H : SK2H) + (uint32_t)r * FLM_ROWB + (uint32_t)(d0 & 63) * 2;
            __nv_bfloat162 h01 = __floats2bfloat162_rn(v.x, v.y);
            __nv_bfloat162 h23 = __floats2bfloat162_rn(v.z, v.w);
            float2 f01 = __bfloat1622float2(h01), f23 = __bfloat1622float2(h23);
            __nv_bfloat162 l01 = __floats2bfloat162_rn(v.x - f01.x, v.y - f01.y);
            __nv_bfloat162 l23 = __floats2bfloat162_rn(v.z - f23.x, v.w - f23.y);
            *(__nv_bfloat162*)(smf + off)        = h01;
            *(__nv_bfloat162*)(smf + off + 4)    = h23;
            *(__nv_bfloat162*)(smf + off + 9216) = l01;
            *(__nv_bfloat162*)(smf + off + 9220) = l23;
        }
#pragma unroll
        for (int u = 0; u < 4; ++u) {
            const int idx = tid + u * 256;
            const int key = idx >> 4, d0 = (idx & 15) * 4;
            const float4 v = *(const float4*)(Vg + (size_t)(b*Sk + kt*64 + key) * ldr + h * 64 + d0);
            const float vv[4] = { v.x, v.y, v.z, v.w };
#pragma unroll
            for (int j = 0; j < 4; ++j) {
                const float f = vv[j];
                __nv_bfloat16 hb = __float2bfloat16(f);
                __nv_bfloat16 lb = __float2bfloat16(f - __bfloat162float(hb));
                const uint32_t o2 = (uint32_t)(d0 + j) * FLM_ROWB + (uint32_t)key * 2;
                *(__nv_bfloat16*)(smf + SVH + o2) = hb;
                *(__nv_bfloat16*)(smf + SVH + 9216 + o2) = lb;
            }
        }
        __syncthreads();

        float S[8][4];
#pragma unroll
        for (int t = 0; t < 8; ++t)
#pragma unroll
            for (int c = 0; c < 4; ++c) S[t][c] = 0.f;

        const uint32_t qB = smb + (mat ? SQ2H : SQ1H);
        const uint32_t kB = smb + (mat ? SK2H : SK1H);
#pragma unroll
        for (int s = 0; s < 4; ++s) {
            uint32_t ah[4], al[4];
            const uint32_t ao = qB + (uint32_t)(slab + g) * FLM_ROWB + s * 32 + qq * 4;
            ah[0] = lds32(ao);              ah[1] = lds32(ao + 8*FLM_ROWB);
            ah[2] = lds32(ao + 16);         ah[3] = lds32(ao + 8*FLM_ROWB + 16);
            al[0] = lds32(ao + 9216);       al[1] = lds32(ao + 9216 + 8*FLM_ROWB);
            al[2] = lds32(ao + 9216 + 16);  al[3] = lds32(ao + 9216 + 8*FLM_ROWB + 16);
#pragma unroll
            for (int nt = 0; nt < 8; ++nt) {
                const uint32_t bo = kB + (uint32_t)(nt*8 + g) * FLM_ROWB + s * 32 + qq * 4;
                uint32_t bh[2], bl[2];
                bh[0] = lds32(bo);        bh[1] = lds32(bo + 16);
                bl[0] = lds32(bo + 9216); bl[1] = lds32(bo + 9216 + 16);
                mma16816(S[nt], ah, bh);
                mma16816(S[nt], ah, bl);
                mma16816(S[nt], al, bh);
            }
        }

        const bool dg = (causal != 0) && (kt == qt);
        uint32_t pH[8][2], pL[8][2];
#pragma unroll
        for (int j = 0; j < 2; ++j) {
            const int rloc = slab + g + j*8;
            float mx = -1e30f;
#pragma unroll
            for (int t = 0; t < 8; ++t) {
                float* sp = &S[t][j*2];
                sp[0] *= 0.125f; sp[1] *= 0.125f;
                if (dg) {
                    const int c = t*8 + qq*2;
                    if (c > rloc)     sp[0] = -1e9f;
                    if (c + 1 > rloc) sp[1] = -1e9f;
                }
                mx = fmaxf(mx, fmaxf(sp[0], sp[1]));
            }
            mx = fmaxf(mx, __shfl_xor_sync(0xffffffffu, mx, 1));
            mx = fmaxf(mx, __shfl_xor_sync(0xffffffffu, mx, 2));
            const float mn = fmaxf(rm[j], mx);
            const float alw = __expf(rm[j] - mn);
            rm[j] = mn;
            float rs = 0.f;
#pragma unroll
            for (int t = 0; t < 8; ++t) {
                const float p0 = __expf(S[t][j*2]   - mn);
                const float p1 = __expf(S[t][j*2+1] - mn);
                rs += p0 + p1;
                __nv_bfloat162 hp = __floats2bfloat162_rn(p0, p1);
                float2 fp = __bfloat1622float2(hp);
                __nv_bfloat162 lp = __floats2bfloat162_rn(p0 - fp.x, p1 - fp.y);
                pH[t][j] = *(uint32_t*)&hp;
                pL[t][j] = *(uint32_t*)&lp;
            }
            rs += __shfl_xor_sync(0xffffffffu, rs, 1);
            rs += __shfl_xor_sync(0xffffffffu, rs, 2);
            rl[j] = rl[j] * alw + rs;
#pragma unroll
            for (int t = 0; t < 8; ++t) { O[t][j*2] *= alw; O[t][j*2+1] *= alw; }
        }

#pragma unroll
        for (int s = 0; s < 4; ++s) {
            const uint32_t aP[4]  = { pH[2*s][0], pH[2*s][1], pH[2*s+1][0], pH[2*s+1][1] };
            const uint32_t aPl[4] = { pL[2*s][0], pL[2*s][1], pL[2*s+1][0], pL[2*s+1][1] };
#pragma unroll
            for (int nt = 0; nt < 8; ++nt) {
                const uint32_t bo = smb + SVH + (uint32_t)(nt*8 + g) * FLM_ROWB + s * 32 + qq * 4;
                uint32_t bh[2], bl[2];
                bh[0] = lds32(bo);        bh[1] = lds32(bo + 16);
                bl[0] = lds32(bo + 9216); bl[1] = lds32(bo + 9216 + 16);
                mma16816(O[nt], aP,  bh);
                mma16816(O[nt], aP,  bl);
                mma16816(O[nt], aPl, bh);
            }
        }
    }

    __syncthreads();
    if (mat == 1) {
#pragma unroll
        for (int j = 0; j < 2; ++j) {
            const float inv = 1.f / rl[j];
            const int row = slab + g + j*8;
#pragma unroll
            for (int t = 0; t < 8; ++t) {
                const int col = t*8 + qq*2;
                float2 w = make_float2(O[t][j*2] * inv, O[t][j*2+1] * inv);
                *(float2*)(smf + SOEX + ((uint32_t)row * 68 + col) * 4) = w;
            }
        }
    }
    __syncthreads();
    if (mat == 0) {
        const float lam = lamp[h];
#pragma unroll
        for (int j = 0; j < 2; ++j) {
            const float inv = 1.f / rl[j];
            const int row = slab + g + j*8;
            float vbuf[16];
            float ss = 0.f;
#pragma unroll
            for (int t = 0; t < 8; ++t) {
                const int col = t*8 + qq*2;
                const float2 w = *(const float2*)(smf + SOEX + ((uint32_t)row * 68 + col) * 4);
                const float v0 = O[t][j*2]   * inv - lam * w.x;
                const float v1 = O[t][j*2+1] * inv - lam * w.y;
                vbuf[2*t] = v0; vbuf[2*t+1] = v1;
                ss += v0*v0 + v1*v1;
            }
            ss += __shfl_xor_sync(0xffffffffu, ss, 1);
            ss += __shfl_xor_sync(0xffffffffu, ss, 2);
            const float scl = rsqrtf(ss * (1.0f/64.0f) + 1e-6f) * 0.2f;
            const size_t ob = ((size_t)(b*Sq + qt*64 + row) * Hh + h) * 64;
#pragma unroll
            for (int t = 0; t < 8; ++t) {
                const int col = t*8 + qq*2;
                const float v0 = vbuf[2*t] * scl, v1 = vbuf[2*t+1] * scl;
                __half2 hh = __floats2half2_rn(v0, v1);
                float2 fh = __half22float2(hh);
                __half2 ll = __floats2half2_rn(v0 - fh.x, v1 - fh.y);
                *(__half2*)(Ohi + ob + col) = hh;
                *(__half2*)(Olo + ob + col) = ll;
            }
        }
    }
}

// ---------------- host-side launch helpers ----------------
static __half *s_wh, *s_ahi, *s_alo, *s_bhi, *s_blo;

static void hgemm(const __half* ahi, const __half* alo, uint32_t woff,
                  const float* R, float* Cf, __half* chi, __half* clo,
                  int M, int N, int K, int ldc, int mode)
{
    dim3 grid(N / 128, M / 128);
    hgemm_kernel<<<grid, 256, HG_SMEM>>>(ahi, alo, s_wh + woff,
                                         R, Cf, chi, clo, M, N, K, ldc, mode);
}

extern "C" void kernel_launch(void* const* d_in, const int* in_sizes, int n_in,
                              void* d_out, int out_size)
{
    const float* x    = (const float*)d_in[0];
    const float* enc  = (const float*)d_in[1];
    const float* Wq_s = (const float*)d_in[2];
    const float* Wk_s = (const float*)d_in[3];
    const float* Wv_s = (const float*)d_in[4];
    const float* Wo_s = (const float*)d_in[5];
    const float* lq1s = (const float*)d_in[6];
    const float* lk1s = (const float*)d_in[7];
    const float* lq2s = (const float*)d_in[8];
    const float* lk2s = (const float*)d_in[9];
    const float* Wq_c = (const float*)d_in[10];
    const float* Wk_c = (const float*)d_in[11];
    const float* Wv_c = (const float*)d_in[12];
    const float* Wo_c = (const float*)d_in[13];
    const float* lq1c = (const float*)d_in[14];
    const float* lk1c = (const float*)d_in[15];
    const float* lq2c = (const float*)d_in[16];
    const float* lk2c = (const float*)d_in[17];
    const float* grms = (const float*)d_in[18];
    const float* W1   = (const float*)d_in[19];
    const float* W2   = (const float*)d_in[20];
    const float* W3   = (const float*)d_in[21];
    float* out = (float*)d_out;

    float *hn, *qkv, *h2, *m1, *lam;
    cudaGetSymbolAddress((void**)&hn,  g_hn);
    cudaGetSymbolAddress((void**)&qkv, g_qkv);
    cudaGetSymbolAddress((void**)&h2,  g_h2);
    cudaGetSymbolAddress((void**)&m1,  g_m1);
    cudaGetSymbolAddress((void**)&lam, g_lam);
    cudaGetSymbolAddress((void**)&s_wh,  g_wh);
    cudaGetSymbolAddress((void**)&s_ahi, g_ahi);
    cudaGetSymbolAddress((void**)&s_alo, g_alo);
    cudaGetSymbolAddress((void**)&s_bhi, g_bhi);
    cudaGetSymbolAddress((void**)&s_blo, g_blo);

    cudaFuncSetAttribute(flash_mma_kernel,
                         cudaFuncAttributeMaxDynamicSharedMemorySize, FLM_SMEM);
    cudaFuncSetAttribute(hgemm_kernel,
                         cudaFuncAttributeMaxDynamicSharedMemorySize, HG_SMEM);

    // ---- weight prep: ALL 11 transposes in ONE launch ----
    {
        WPack p;
        // starts: cumulative block counts; blocks_i = (N/32)*(K/32)
        p.d[0]  = { Wq_s, OW_QS, 1024, 2048, 0     };  // 2048
        p.d[1]  = { Wk_s, OW_KS, 1024, 2048, 2048  };  // 2048
        p.d[2]  = { Wv_s, OW_VS, 1024, 1024, 4096  };  // 1024
        p.d[3]  = { Wo_s, OW_OS, 1024, 1024, 5120  };  // 1024
        p.d[4]  = { Wq_c, OW_QC, 1024, 2048, 6144  };  // 2048
        p.d[5]  = { Wk_c, OW_KC, 1024, 2048, 8192  };  // 2048
        p.d[6]  = { Wv_c, OW_VC, 1024, 1024, 10240 };  // 1024
        p.d[7]  = { Wo_c, OW_OC, 1024, 1024, 11264 };  // 1024
        p.d[8]  = { W1,   OW_W1, 1024, 4096, 12288 };  // 4096
        p.d[9]  = { W2,   OW_W2, 1024, 4096, 16384 };  // 4096
        p.d[10] = { W3,   OW_W3, 4096, 1024, 20480 };  // 4096  -> total 24576
        split_all_kernel<<<24576, dim3(32, 8)>>>(p, s_wh);
    }

    lambda2_kernel<<<32, 32>>>(lq1s, lk1s, lq2s, lk2s, lq1c, lk1c, lq2c, lk2c, lam);

    // h = rmsnorm(x, g) -> fp32 hn (residual) + fp16 split in A
    rmsnorm_h_kernel<<<ROWS, 256>>>(x, grms, hn, (__half2*)s_ahi, (__half2*)s_alo);

    // ---- self diff-attention (causal): merged QKV GEMM (N=5120) ----
    hgemm(s_ahi, s_alo, OW_QS, nullptr, qkv, nullptr, nullptr, ROWS, 5120, 1024, 5120, 0);
    flash_mma_kernel<<<dim3(Tt/64, Hh, Bb), 256, FLM_SMEM>>>(qkv, qkv + 2048, qkv + 4096,
        lam, s_bhi, s_blo, Tt, Tt, 1, 5120);
    // h1 = ao @ Wo_s + hn  -> fp16 split into A
    hgemm(s_bhi, s_blo, OW_OS, hn, nullptr, s_ahi, s_alo, ROWS, 1024, 1024, 1024, 1);

    // ---- cross diff-attention (not causal) ----
    hgemm(s_ahi, s_alo, OW_QC, nullptr, qkv, nullptr, nullptr, ROWS, 2048, 1024, 5120, 0);
    split_h_kernel<<<(ROWS*1024/4)/256, 256>>>((const float4*)enc,
        (__half2*)s_bhi, (__half2*)s_blo, ROWS*1024/4);
    // merged K|V GEMM (N=3072) into qkv cols 2048..5119
    hgemm(s_bhi, s_blo, OW_KC, nullptr, qkv + 2048, nullptr, nullptr, ROWS, 3072, 1024, 5120, 0);
    flash_mma_kernel<<<dim3(Tt/64, Hh, Bb), 256, FLM_SMEM>>>(qkv, qkv + 2048, qkv + 4096,
        lam + 16, s_ahi, s_alo, Tt, Tt, 0, 5120);
    // h2 = 2 * (ao @ Wo_c) -> fp32 (residual + rmsnorm input)
    hgemm(s_ahi, s_alo, OW_OC, nullptr, h2, nullptr, nullptr, ROWS, 1024, 1024, 1024, 2);

    // ---- MLP (fp16 2-term path) ----
    rmsnorm_h_kernel<<<ROWS, 256>>>(h2, grms, nullptr, (__half2*)s_bhi, (__half2*)s_blo);
    hgemm(s_bhi, s_blo, OW_W1, nullptr, m1, nullptr, nullptr, ROWS, DFF, 1024, DFF, 0);
    hgemm(s_bhi, s_blo, OW_W2, m1, nullptr, s_ahi, s_alo, ROWS, DFF, 1024, DFF, 5);
    hgemm(s_ahi, s_alo, OW_W3, h2, out, nullptr, nullptr, ROWS, 1024, DFF, 1024, 1);
}